// round 1
// baseline (speedup 1.0000x reference)
#include <cuda_runtime.h>
#include <cuda_bf16.h>

// TorchBSplineBasis: out[b, i*10+j] = A_b[i] * B_b[j], where A/B are cubic
// B-spline bases (NUM_BASIS=10, DEGREE=3, 14 knots/dim) of t[b,0], t[b,1].
//
// Strategy: store-bound (200 MB out). One thread computes one row's two
// 10-vector bases via Cox-de Boor with precomputed reciprocals; results go
// through SMEM so the block can emit fully coalesced float4 stores.

#define ROWS_PER_BLOCK 128
#define NB 10
#define NKNOT 14
// pair-table sizes per degree level: k=1 -> 12, k=2 -> 11, k=3 -> 10 (total 33)
#define NPAIRS 33

__global__ __launch_bounds__(ROWS_PER_BLOCK)
void bspline_basis_kernel(const float* __restrict__ t,
                          const float* __restrict__ knots,
                          float* __restrict__ out,
                          int rows)
{
    __shared__ float s_kn[2][NKNOT];
    __shared__ float s_inv1[2][NPAIRS];
    __shared__ float s_inv2[2][NPAIRS];
    __shared__ float sA[ROWS_PER_BLOCK][11];   // stride 11: bank-conflict padding
    __shared__ float sB[ROWS_PER_BLOCK][11];

    const int tid = threadIdx.x;

    // ---- load knots (2 x 14 floats) ----
    if (tid < 2 * NKNOT) {
        s_kn[tid / NKNOT][tid % NKNOT] = knots[tid];
    }
    __syncthreads();

    // ---- build reciprocal tables (matches jnp.where(d==0, 0, 1/d)) ----
    if (tid < 2 * NPAIRS) {
        int d = tid / NPAIRS;
        int p = tid % NPAIRS;
        int k, i;
        if (p < 12)      { k = 1; i = p; }
        else if (p < 23) { k = 2; i = p - 12; }
        else             { k = 3; i = p - 23; }
        float d1 = s_kn[d][i + k]     - s_kn[d][i];
        float d2 = s_kn[d][i + k + 1] - s_kn[d][i + 1];
        s_inv1[d][p] = (d1 == 0.0f) ? 0.0f : 1.0f / d1;
        s_inv2[d][p] = (d2 == 0.0f) ? 0.0f : 1.0f / d2;
    }
    __syncthreads();

    const int row0 = blockIdx.x * ROWS_PER_BLOCK;
    const int row  = row0 + tid;

    if (row < rows) {
        // coalesced float2 load of (t0, t1)
        const float2 tv = *reinterpret_cast<const float2*>(t + (size_t)row * 2);
        const float tt[2] = { tv.x, tv.y };

        #pragma unroll
        for (int d = 0; d < 2; d++) {
            const float tc = tt[d];
            float Bv[13];
            // degree-0: indicator of half-open knot intervals
            #pragma unroll
            for (int i = 0; i < 13; i++) {
                Bv[i] = (s_kn[d][i] <= tc && tc < s_kn[d][i + 1]) ? 1.0f : 0.0f;
            }
            // Cox-de Boor DP, degrees 1..3
            int base = 0;
            #pragma unroll
            for (int k = 1; k <= 3; k++) {
                const int m = 13 - k;
                #pragma unroll
                for (int i = 0; i < m; i++) {
                    float w1 = (tc - s_kn[d][i])         * s_inv1[d][base + i];
                    float w2 = (s_kn[d][i + k + 1] - tc) * s_inv2[d][base + i];
                    Bv[i] = w1 * Bv[i] + w2 * Bv[i + 1];
                }
                base += m;
            }
            float* dst = (d == 0) ? sA[tid] : sB[tid];
            #pragma unroll
            for (int i = 0; i < NB; i++) dst[i] = Bv[i];
        }
    }
    __syncthreads();

    // ---- cooperative coalesced store of the 128x100 tile via float4 ----
    const int tileRows = min(ROWS_PER_BLOCK, rows - row0);
    const int nvec = tileRows * 25;                  // 100 floats = 25 float4 per row
    float4* outv = reinterpret_cast<float4*>(out + (size_t)row0 * 100);

    for (int v = tid; v < nvec; v += ROWS_PER_BLOCK) {
        const int r = v / 25;
        const int c = (v - r * 25) * 4;
        float4 o;
        {
            int k0 = c;
            o.x = sA[r][(k0    ) / 10] * sB[r][(k0    ) % 10];
            o.y = sA[r][(k0 + 1) / 10] * sB[r][(k0 + 1) % 10];
            o.z = sA[r][(k0 + 2) / 10] * sB[r][(k0 + 2) % 10];
            o.w = sA[r][(k0 + 3) / 10] * sB[r][(k0 + 3) % 10];
        }
        outv[v] = o;
    }
}

extern "C" void kernel_launch(void* const* d_in, const int* in_sizes, int n_in,
                              void* d_out, int out_size) {
    const float* t     = (const float*)d_in[0];   // (BATCH, 2) fp32
    const float* knots = (const float*)d_in[1];   // (2, 14) fp32
    float* out = (float*)d_out;                   // (BATCH, 100) fp32

    const int rows = in_sizes[0] / 2;
    const int grid = (rows + ROWS_PER_BLOCK - 1) / ROWS_PER_BLOCK;
    bspline_basis_kernel<<<grid, ROWS_PER_BLOCK>>>(t, knots, out, rows);
}

// round 3
// speedup vs baseline: 1.1043x; 1.1043x over previous
#include <cuda_runtime.h>
#include <cuda_bf16.h>
#include <cstdint>

// TorchBSplineBasis: out[b, i*10+j] = A_b[i] * B_b[j], cubic B-spline bases
// (NUM_BASIS=10, DEGREE=3, 14 knots/dim) of t[b,0], t[b,1].
//
// R2 strategy (resubmit; previous bench was a broker-capacity timeout):
// per-thread row -> products with compile-time indices -> SMEM in exact gmem
// layout (stride 100 floats; STS.128 conflict-free since 100 mod 32 = 4
// spreads 8-lane phases over distinct bank quads) -> single TMA bulk store
// per block (cp.async.bulk), eliminating the scalar copy loop.

#define ROWS_PER_BLOCK 128
#define NB 10
#define NKNOT 14
#define NPAIRS 33           // 12 (k=1) + 11 (k=2) + 10 (k=3)
#define ROW_FLOATS 100
#define SMEM_PROD_BYTES (ROWS_PER_BLOCK * ROW_FLOATS * 4)   // 51200

__device__ __forceinline__ uint32_t smem_u32(const void* p) {
    uint32_t a;
    asm("{ .reg .u64 t; cvta.to.shared.u64 t, %1; cvt.u32.u64 %0, t; }"
        : "=r"(a) : "l"(p));
    return a;
}

__global__ __launch_bounds__(ROWS_PER_BLOCK)
void bspline_basis_kernel(const float* __restrict__ t,
                          const float* __restrict__ knots,
                          float* __restrict__ out,
                          int rows)
{
    extern __shared__ float s_prod[];          // [ROWS_PER_BLOCK][100], gmem layout
    __shared__ float s_kn[2][NKNOT];
    __shared__ float s_inv1[2][NPAIRS];
    __shared__ float s_inv2[2][NPAIRS];

    const int tid = threadIdx.x;

    if (tid < 2 * NKNOT) {
        s_kn[tid / NKNOT][tid % NKNOT] = knots[tid];
    }
    __syncthreads();

    // reciprocal tables, matching jnp.where(d==0, 0, 1/d)
    if (tid < 2 * NPAIRS) {
        int d = tid / NPAIRS;
        int p = tid % NPAIRS;
        int k, i;
        if (p < 12)      { k = 1; i = p; }
        else if (p < 23) { k = 2; i = p - 12; }
        else             { k = 3; i = p - 23; }
        float d1 = s_kn[d][i + k]     - s_kn[d][i];
        float d2 = s_kn[d][i + k + 1] - s_kn[d][i + 1];
        s_inv1[d][p] = (d1 == 0.0f) ? 0.0f : 1.0f / d1;
        s_inv2[d][p] = (d2 == 0.0f) ? 0.0f : 1.0f / d2;
    }
    __syncthreads();

    const int row0 = blockIdx.x * ROWS_PER_BLOCK;
    const int row  = row0 + tid;

    if (row < rows) {
        const float2 tv = *reinterpret_cast<const float2*>(t + (size_t)row * 2);
        const float tt[2] = { tv.x, tv.y };

        float A[NB], Bb[NB];

        #pragma unroll
        for (int d = 0; d < 2; d++) {
            const float tc = tt[d];
            float Bv[13];
            #pragma unroll
            for (int i = 0; i < 13; i++) {
                Bv[i] = (s_kn[d][i] <= tc && tc < s_kn[d][i + 1]) ? 1.0f : 0.0f;
            }
            int base = 0;
            #pragma unroll
            for (int k = 1; k <= 3; k++) {
                const int m = 13 - k;
                #pragma unroll
                for (int i = 0; i < m; i++) {
                    float w1 = (tc - s_kn[d][i])         * s_inv1[d][base + i];
                    float w2 = (s_kn[d][i + k + 1] - tc) * s_inv2[d][base + i];
                    Bv[i] = w1 * Bv[i] + w2 * Bv[i + 1];
                }
                base += m;
            }
            float* dst = (d == 0) ? A : Bb;
            #pragma unroll
            for (int i = 0; i < NB; i++) dst[i] = Bv[i];
        }

        // outer product, compile-time (i,j); STS.128 into gmem-layout SMEM
        float* dst = s_prod + tid * ROW_FLOATS;
        #pragma unroll
        for (int e = 0; e < ROW_FLOATS; e += 4) {
            float4 o;
            o.x = A[(e    ) / 10] * Bb[(e    ) % 10];
            o.y = A[(e + 1) / 10] * Bb[(e + 1) % 10];
            o.z = A[(e + 2) / 10] * Bb[(e + 2) % 10];
            o.w = A[(e + 3) / 10] * Bb[(e + 3) % 10];
            *reinterpret_cast<float4*>(dst + e) = o;
        }
    }
    __syncthreads();

    // one TMA bulk store: SMEM image is byte-identical to the gmem destination
    if (tid == 0) {
        const int tileRows = min(ROWS_PER_BLOCK, rows - row0);
        const uint32_t bytes = (uint32_t)tileRows * (ROW_FLOATS * 4);
        const uint32_t saddr = smem_u32(s_prod);
        const uint64_t gaddr = (uint64_t)(uintptr_t)(out + (size_t)row0 * ROW_FLOATS);

        asm volatile("fence.proxy.async.shared::cta;" ::: "memory");
        asm volatile("cp.async.bulk.global.shared::cta.bulk_group [%0], [%1], %2;"
                     :: "l"(gaddr), "r"(saddr), "r"(bytes) : "memory");
        asm volatile("cp.async.bulk.commit_group;" ::: "memory");
        asm volatile("cp.async.bulk.wait_group.read 0;" ::: "memory");
    }
}

extern "C" void kernel_launch(void* const* d_in, const int* in_sizes, int n_in,
                              void* d_out, int out_size) {
    const float* t     = (const float*)d_in[0];   // (BATCH, 2) fp32
    const float* knots = (const float*)d_in[1];   // (2, 14) fp32
    float* out = (float*)d_out;                   // (BATCH, 100) fp32

    const int rows = in_sizes[0] / 2;
    const int grid = (rows + ROWS_PER_BLOCK - 1) / ROWS_PER_BLOCK;

    static bool attr_set = false;   // idempotent host-side attribute, not a work guard
    if (!attr_set) {
        cudaFuncSetAttribute(bspline_basis_kernel,
                             cudaFuncAttributeMaxDynamicSharedMemorySize,
                             SMEM_PROD_BYTES);
        attr_set = true;
    }

    bspline_basis_kernel<<<grid, ROWS_PER_BLOCK, SMEM_PROD_BYTES>>>(t, knots, out, rows);
}